// round 2
// baseline (speedup 1.0000x reference)
#include <cuda_runtime.h>
#include <math.h>

// Problem constants
#define BB 256
#define TT 1000
#define NN 200
#define NII 7
#define HK 100              // k-range per half-thread

#define ALPHA_F 0.2f
#define OMA_F   0.8f
#define NSC_F   0.0948683292f   // 0.15*sqrt(2*0.2)

// packed fp32x2 FMA: acc.lo += w.lo*ylo ; acc.hi += w.hi*yhi
__device__ __forceinline__ void ffma2(unsigned long long& acc, unsigned long long w,
                                      float ylo, float yhi) {
    asm("{\n\t"
        ".reg .b64 yy;\n\t"
        "mov.b64 yy, {%2, %3};\n\t"
        "fma.rn.f32x2 %0, %1, yy, %0;\n\t"
        "}"
        : "+l"(acc) : "l"(w), "f"(ylo), "f"(yhi));
}

__device__ __forceinline__ float hsum2(unsigned long long a) {
    float2 f;
    asm("mov.b64 {%0, %1}, %2;" : "=f"(f.x), "=f"(f.y) : "l"(a));
    return f.x + f.y;
}

__global__ void __launch_bounds__(512, 1)
rnn_persistent_kernel(const float* __restrict__ y0,
                      const float* __restrict__ u_seq,
                      const float* __restrict__ noise,
                      const float* __restrict__ W_in_raw,
                      const float* __restrict__ W_rec,
                      const float* __restrict__ b_rec,
                      const float* __restrict__ w_out,
                      const float* __restrict__ b_out,
                      float* __restrict__ out)
{
    __shared__ __align__(16) float y_s[2][2][NN];   // [buf][row][neuron]
    __shared__ float p_s[2][NN + 1];                // partial dots from half1 (incl drive)
    __shared__ float u_s[2][2][NII];                // [buf][row][input]
    __shared__ float wia_s[NN * 9];                 // |W_in| padded stride 9 (conflict-free)

    const int tid = threadIdx.x;
    const int h   = tid >> 8;          // k-half: 0 or 1
    const int n   = tid & 255;         // neuron id (or 200 = z)
    const bool is_neuron = (n <  NN);
    const bool is_z      = (n == NN);
    const bool active    = (n <= NN);
    const int  b0 = blockIdx.x * 2;
    const int  b1 = b0 + 1;
    const int  koff = h * HK;

    float* __restrict__ y_seq = out;
    float* __restrict__ z_seq = out + (size_t)BB * TT * NN;
    float* __restrict__ y_fin = out + (size_t)BB * TT * NN + (size_t)BB * TT;

    // ---- |W_in| -> padded SMEM (cooperative) ----
    for (int idx = tid; idx < NN * NII; idx += 512) {
        int nn = idx / NII, i = idx % NII;
        wia_s[nn * 9 + i] = fabsf(W_in_raw[idx]);
    }

    // ---- register-resident HALF weight row (100 fp32 = 50 x b64) ----
    unsigned long long w[HK / 2];
    float brec = 0.f, bout = 0.f;
    if (active) {
        const float* base = is_z ? (w_out + koff)
                                 : (W_rec + (size_t)n * NN + koff);
        const unsigned long long* wp = reinterpret_cast<const unsigned long long*>(base);
        #pragma unroll
        for (int m = 0; m < HK / 2; ++m) w[m] = __ldg(&wp[m]);
        if (is_neuron) brec = b_rec[n];
        else           bout = b_out[0];
    }
    if (h == 0 && is_neuron) {
        y_s[0][0][n] = y0[(size_t)b0 * NN + n];
        y_s[0][1][n] = y0[(size_t)b1 * NN + n];
    }
    if (tid < 2 * NII) {
        int bl = tid / NII, i = tid % NII;
        u_s[0][bl][i] = u_seq[((size_t)(b0 + bl) * TT) * NII + i];
    }
    float nz0 = 0.f, nz1 = 0.f;
    if (h == 0 && is_neuron) {
        nz0 = noise[((size_t)b0 * TT) * NN + n];
        nz1 = noise[((size_t)b1 * TT) * NN + n];
    }
    __syncthreads();

    int buf = 0;
    for (int t = 0; t < TT; ++t) {
        // ---- prefetch next step noise / u (one step of latency hiding) ----
        float nz0n = 0.f, nz1n = 0.f, un = 0.f;
        if (h == 0 && is_neuron && (t + 1 < TT)) {
            nz0n = __ldcs(&noise[((size_t)b0 * TT + (t + 1)) * NN + n]);
            nz1n = __ldcs(&noise[((size_t)b1 * TT + (t + 1)) * NN + n]);
        }
        if (tid < 2 * NII && (t + 1 < TT)) {
            int bl = tid / NII, i = tid % NII;
            un = __ldcs(&u_seq[((size_t)(b0 + bl) * TT + (t + 1)) * NII + i]);
        }

        float pre0 = 0.f, pre1 = 0.f;
        if (active) {
            // half-dot over k in [koff, koff+100): 4 independent FFMA2 chains
            const float4* Y0 = reinterpret_cast<const float4*>(y_s[buf][0] + koff);
            const float4* Y1 = reinterpret_cast<const float4*>(y_s[buf][1] + koff);
            unsigned long long c0a = 0ull, c0b = 0ull, c1a = 0ull, c1b = 0ull;
            #pragma unroll
            for (int m = 0; m < HK / 4; ++m) {
                float4 p = Y0[m];
                float4 q = Y1[m];
                ffma2(c0a, w[2 * m],     p.x, p.y);
                ffma2(c0b, w[2 * m + 1], p.z, p.w);
                ffma2(c1a, w[2 * m],     q.x, q.y);
                ffma2(c1b, w[2 * m + 1], q.z, q.w);
            }
            pre0 = hsum2(c0a) + hsum2(c0b);
            pre1 = hsum2(c1a) + hsum2(c1b);

            if (h == 1) {
                if (is_neuron) {
                    // half1 folds input drive + b_rec into its partial
                    float dr0 = brec, dr1 = brec;
                    #pragma unroll
                    for (int i = 0; i < NII; ++i) {
                        float wv = wia_s[n * 9 + i];
                        dr0 = fmaf(wv, u_s[buf][0][i], dr0);
                        dr1 = fmaf(wv, u_s[buf][1][i], dr1);
                    }
                    pre0 += dr0; pre1 += dr1;
                } else {
                    pre0 += bout; pre1 += bout;
                }
                p_s[0][n] = pre0;
                p_s[1][n] = pre1;
            }
        }
        if (tid < 2 * NII && (t + 1 < TT)) {
            int bl = tid / NII, i = tid % NII;
            u_s[buf ^ 1][bl][i] = un;
        }
        __syncthreads();   // half1 partials (and next u) visible

        if (h == 0 && active) {
            float f0 = pre0 + p_s[0][n];
            float f1 = pre1 + p_s[1][n];
            if (is_neuron) {
                float yp0 = y_s[buf][0][n];
                float yp1 = y_s[buf][1][n];
                float r0 = fmaxf(f0, 0.f);
                float r1 = fmaxf(f1, 0.f);
                float yn0 = fmaf(OMA_F, yp0, fmaf(ALPHA_F, r0, NSC_F * nz0));
                float yn1 = fmaf(OMA_F, yp1, fmaf(ALPHA_F, r1, NSC_F * nz1));
                y_s[buf ^ 1][0][n] = yn0;
                y_s[buf ^ 1][1][n] = yn1;
                __stcs(&y_seq[((size_t)b0 * TT + t) * NN + n], yn0);
                __stcs(&y_seq[((size_t)b1 * TT + t) * NN + n], yn1);
                nz0 = nz0n; nz1 = nz1n;
            } else if (t >= 1) {
                // dot was over y_{t-1}
                z_seq[(size_t)b0 * TT + (t - 1)] = 1.f / (1.f + expf(-f0));
                z_seq[(size_t)b1 * TT + (t - 1)] = 1.f / (1.f + expf(-f1));
            }
        }
        __syncthreads();   // new y visible before next dot
        buf ^= 1;
    }

    // ---- tails ----
    if (h == 0 && is_neuron) {
        y_fin[(size_t)b0 * NN + n] = y_s[buf][0][n];
        y_fin[(size_t)b1 * NN + n] = y_s[buf][1][n];
    }
    // final z over y_{T-1} (= y_s[buf])
    float zp0 = 0.f, zp1 = 0.f;
    if (is_z) {
        const float4* Y0 = reinterpret_cast<const float4*>(y_s[buf][0] + koff);
        const float4* Y1 = reinterpret_cast<const float4*>(y_s[buf][1] + koff);
        unsigned long long c0a = 0ull, c0b = 0ull, c1a = 0ull, c1b = 0ull;
        #pragma unroll
        for (int m = 0; m < HK / 4; ++m) {
            float4 p = Y0[m];
            float4 q = Y1[m];
            ffma2(c0a, w[2 * m],     p.x, p.y);
            ffma2(c0b, w[2 * m + 1], p.z, p.w);
            ffma2(c1a, w[2 * m],     q.x, q.y);
            ffma2(c1b, w[2 * m + 1], q.z, q.w);
        }
        zp0 = hsum2(c0a) + hsum2(c0b);
        zp1 = hsum2(c1a) + hsum2(c1b);
        if (h == 1) {
            p_s[0][NN] = zp0 + bout;
            p_s[1][NN] = zp1 + bout;
        }
    }
    __syncthreads();
    if (is_z && h == 0) {
        z_seq[(size_t)b0 * TT + (TT - 1)] = 1.f / (1.f + expf(-(zp0 + p_s[0][NN])));
        z_seq[(size_t)b1 * TT + (TT - 1)] = 1.f / (1.f + expf(-(zp1 + p_s[1][NN])));
    }
}

extern "C" void kernel_launch(void* const* d_in, const int* in_sizes, int n_in,
                              void* d_out, int out_size) {
    const float* y0       = (const float*)d_in[0];
    const float* u_seq    = (const float*)d_in[1];
    const float* noise    = (const float*)d_in[2];
    const float* W_in_raw = (const float*)d_in[3];
    const float* W_rec    = (const float*)d_in[4];
    const float* b_rec    = (const float*)d_in[5];
    const float* w_out    = (const float*)d_in[6];
    const float* b_out    = (const float*)d_in[7];
    float* out = (float*)d_out;

    rnn_persistent_kernel<<<BB / 2, 512>>>(y0, u_seq, noise, W_in_raw, W_rec,
                                           b_rec, w_out, b_out, out);
}